// round 12
// baseline (speedup 1.0000x reference)
#include <cuda_runtime.h>
#include <cstdint>

// ---------------- problem constants ----------------
#define NE   8
#define NT   16384
#define NIN  2048
#define NOUT 2048

// ---------------- GEMM tiling (R9-identical) ----------------
#define BM 128
#define BN 256
#define BK 32
#define KITERS (NIN / BK)            // 64
#define STAGES 4
#define A_STAGE_BYTES (BM * BK * 4)  // 16384
#define B_STAGE_BYTES (BN * BK * 4)  // 32768
#define STAGE_BYTES (A_STAGE_BYTES + B_STAGE_BYTES)   // 49152
#define SMEM_CTRL 1024
#define SMEM_TOTAL (SMEM_CTRL + STAGES * STAGE_BYTES) // 197632
#define NTHREADS 320                 // 8 compute warps + 2 producer warps

// ---------------- scratch: tf32-rounded, fragment-native layouts ----------------
__device__ float g_A[(size_t)NT * NIN];
__device__ float g_W[(size_t)NE * NOUT * NIN];

// ---------------- helpers (all plain-sm_103-legal) ----------------
__device__ __forceinline__ uint32_t smem_u32(const void* p) {
    uint32_t a;
    asm("{ .reg .u64 t; cvta.to.shared.u64 t, %1; cvt.u32.u64 %0, t; }" : "=r"(a) : "l"(p));
    return a;
}

__device__ __forceinline__ float tf32r(float f) {
    uint32_t r;
    asm("cvt.rna.tf32.f32 %0, %1;" : "=r"(r) : "f"(f));
    return __uint_as_float(r);
}

__device__ __forceinline__ void cp16(uint32_t smem_dst, const float* gsrc) {
    asm volatile("cp.async.cg.shared.global [%0], [%1], 16;" :: "r"(smem_dst), "l"(gsrc));
}

#define MBAR_INIT(a, c) \
    asm volatile("mbarrier.init.shared.b64 [%0], %1;" :: "r"(a), "r"(c) : "memory")
#define MBAR_ARRIVE(a) \
    asm volatile("mbarrier.arrive.shared.b64 _, [%0];" :: "r"(a) : "memory")
#define CP_MBAR_ARRIVE(a) \
    asm volatile("cp.async.mbarrier.arrive.noinc.shared.b64 [%0];" :: "r"(a) : "memory")

#define MBAR_WAIT(addr, ph) do {                                                   \
    asm volatile("{\n\t.reg .pred P1;\n\t"                                         \
        "WL%=:\n\t"                                                                \
        "mbarrier.try_wait.parity.acquire.cta.shared::cta.b64 P1, [%0], %1, 0x989680;\n\t" \
        "@P1 bra.uni WD%=;\n\t"                                                    \
        "bra.uni WL%=;\n\t"                                                        \
        "WD%=:\n\t}"                                                               \
        :: "r"(addr), "r"(ph) : "memory");                                         \
} while (0)

__device__ __forceinline__ void lds128(uint32_t* r, uint32_t addr) {
    asm volatile("ld.shared.v4.b32 {%0,%1,%2,%3}, [%4];"
                 : "=r"(r[0]), "=r"(r[1]), "=r"(r[2]), "=r"(r[3]) : "r"(addr));
}
__device__ __forceinline__ void lds64(uint32_t* r, uint32_t addr) {
    asm volatile("ld.shared.v2.b32 {%0,%1}, [%2];"
                 : "=r"(r[0]), "=r"(r[1]) : "r"(addr));
}

__device__ __forceinline__ void mma_tf32(float* d, const uint32_t* a, const uint32_t* b) {
    asm volatile(
        "mma.sync.aligned.m16n8k8.row.col.f32.tf32.tf32.f32 "
        "{%0,%1,%2,%3}, {%4,%5,%6,%7}, {%8,%9}, {%0,%1,%2,%3};"
        : "+f"(d[0]), "+f"(d[1]), "+f"(d[2]), "+f"(d[3])
        : "r"(a[0]), "r"(a[1]), "r"(a[2]), "r"(a[3]), "r"(b[0]), "r"(b[1]));
}

// tile index -> (e, mt, start, mycnt); returns false past the end
__device__ __forceinline__ bool map_tile(const int* __restrict__ tpe, int ti,
                                         int& e, int& mt, int& start, int& mycnt) {
    int acc = 0, sacc = 0;
    e = -1;
    #pragma unroll
    for (int i = 0; i < NE; i++) {
        int cc = __ldg(tpe + i);
        int tiles = (cc + BM - 1) >> 7;
        if (e < 0 && ti < acc + tiles) { e = i; mt = ti - acc; start = sacc; mycnt = cc; }
        acc += tiles; sacc += cc;
    }
    return e >= 0;
}

// ---------------- coalesced pre-pass (R9-identical, proven) ---------------------
__global__ void __launch_bounds__(256) prep_kernel(const float* __restrict__ x,
                                                   const float* __restrict__ w) {
    __shared__ float s[64 * 68];
    const int tid = threadIdx.x;
    const bool isA = blockIdx.x < 8192;
    const int bi = isA ? blockIdx.x : blockIdx.x - 8192;
    const int rowbase = (bi >> 5) * 64;
    const int colbase = (bi & 31) * 64;
    const float* src = (isA ? x : w) + (size_t)rowbase * NIN + colbase;

    #pragma unroll
    for (int it = 0; it < 4; it++) {
        int L = tid + it * 256;
        int row = L >> 4, ch = L & 15;
        float4 v = *(const float4*)(src + (size_t)row * NIN + ch * 4);
        *(float4*)(&s[row * 68 + ch * 4]) = v;
    }
    __syncthreads();

    const int lane = tid & 31;
    const int wrp  = tid >> 5;
    if (isA) {
        const int b   = rowbase >> 7;
        const int mtb = (rowbase >> 4) & 7;
        const int kc  = (colbase >> 3) + wrp;
        const int lrg = lane >> 2, q = lane & 3;
        const int c   = wrp * 8 + q;
        #pragma unroll
        for (int r = 0; r < 4; r++) {
            const int r0 = r * 16 + lrg;
            float4 o;
            o.x = tf32r(s[r0 * 68 + c]);
            o.y = tf32r(s[(r0 + 8) * 68 + c]);
            o.z = tf32r(s[r0 * 68 + c + 4]);
            o.w = tf32r(s[(r0 + 8) * 68 + c + 4]);
            *(float4*)(g_A + (((size_t)b * 256 + kc) * 8 + (mtb + r)) * 128
                       + lane * 4) = o;
        }
    } else {
        const int nb  = rowbase >> 8;
        const int ntb = (rowbase >> 3) & 31;
        const int kc  = (colbase >> 3) + wrp;
        const int l2  = lane & 15;
        const int hw  = lane >> 4;
        const int ln  = l2 >> 1;
        const int d0  = (l2 & 1) * 4;
        #pragma unroll
        for (int r = 0; r < 4; r++) {
            const int ntL = r * 2 + hw;
            const int row = ntL * 8 + ln;
            const float* sr = &s[row * 68 + wrp * 8];
            float4 o;
            o.x = tf32r(sr[((d0 + 0) >> 1) + 4 * ((d0 + 0) & 1)]);
            o.y = tf32r(sr[((d0 + 1) >> 1) + 4 * ((d0 + 1) & 1)]);
            o.z = tf32r(sr[((d0 + 2) >> 1) + 4 * ((d0 + 2) & 1)]);
            o.w = tf32r(sr[((d0 + 3) >> 1) + 4 * ((d0 + 3) & 1)]);
            *(float4*)(g_W + (((size_t)nb * 256 + kc) * 32 + (ntb + ntL)) * 64
                       + l2 * 4) = o;
        }
    }
}

// ---------------- persistent grouped GEMM: R9 pipeline + tile loop --------------
__global__ void __launch_bounds__(NTHREADS, 1) gemm_kernel(
        const float* __restrict__ bias,
        const int*   __restrict__ tpe,
        float*       __restrict__ out) {
    extern __shared__ __align__(16) char smem[];

    // total active tiles (uniform across CTAs)
    int ttiles;
    {
        int acc = 0;
        #pragma unroll
        for (int i = 0; i < NE; i++) acc += (__ldg(tpe + i) + BM - 1) >> 7;
        ttiles = acc * 8;
    }

    const int tid = threadIdx.x;
    const uint32_t sb     = smem_u32(smem);
    const uint32_t fullb  = sb;
    const uint32_t emptyb = sb + 64;
    const uint32_t dbase  = sb + SMEM_CTRL;

    if (tid == 0) {
        #pragma unroll
        for (int s = 0; s < STAGES; s++) {
            MBAR_INIT(fullb + s * 8, 64);
            MBAR_INIT(emptyb + s * 8, 256);
        }
    }
    __syncthreads();

    if (tid >= 256) {
        // ================= producer warps (2 warps, 64 threads) =================
        const int ptid = tid - 256;
        unsigned gk = 0;                         // global k-iter counter (ring state)
        #pragma unroll 1
        for (int tile = blockIdx.x; tile < ttiles; tile += gridDim.x) {
            const int ti = tile >> 3, nt = tile & 7;
            int e, mt, start, mycnt;
            map_tile(tpe, ti, e, mt, start, mycnt);
            const float* Ab = g_A + (size_t)((start >> 7) + mt) * 256 * 1024;
            const float* Bb = g_W + (size_t)(e * 8 + nt) * 256 * 2048;
            #pragma unroll 1
            for (int k = 0; k < KITERS; k++, gk++) {
                const int s = gk & (STAGES - 1);
                if (gk >= STAGES) MBAR_WAIT(emptyb + s * 8, ((gk >> 2) - 1) & 1);
                const float* As = Ab + (size_t)k * 4096;
                const float* Bs = Bb + (size_t)k * 8192;
                const uint32_t dA = dbase + s * STAGE_BYTES;
                const uint32_t dB = dA + A_STAGE_BYTES;
                #pragma unroll
                for (int i = 0; i < 16; i++)
                    cp16(dA + (ptid + i * 64) * 16, As + (ptid + i * 64) * 4);
                #pragma unroll
                for (int i = 0; i < 32; i++)
                    cp16(dB + (ptid + i * 64) * 16, Bs + (ptid + i * 64) * 4);
                CP_MBAR_ARRIVE(fullb + s * 8);
            }
        }
    } else {
        // ================= compute warps (8 warps, 256 threads) =================
        const int lane = tid & 31;
        const int wid  = tid >> 5;
        const int wm   = wid & 1;
        const int wn   = wid >> 1;

        unsigned gk = 0;
        #pragma unroll 1
        for (int tile = blockIdx.x; tile < ttiles; tile += gridDim.x) {
            const int ti = tile >> 3, nt = tile & 7;
            int e, mt, start, mycnt;
            map_tile(tpe, ti, e, mt, start, mycnt);
            const int m0 = start + mt * BM;

            float acc[4][8][4];
            #pragma unroll
            for (int i = 0; i < 4; i++)
                #pragma unroll
                for (int j = 0; j < 8; j++)
                    #pragma unroll
                    for (int q = 0; q < 4; q++) acc[i][j][q] = 0.0f;

            #pragma unroll 1
            for (int k = 0; k < KITERS; k++, gk++) {
                const int s = gk & (STAGES - 1);
                MBAR_WAIT(fullb + s * 8, (gk >> 2) & 1);
                const uint32_t aBase = dbase + s * STAGE_BYTES;
                const uint32_t bBase = aBase + A_STAGE_BYTES;
                #pragma unroll
                for (int kcl = 0; kcl < 4; kcl++) {
                    uint32_t af[4][4], bf[8][2];
                    #pragma unroll
                    for (int i = 0; i < 4; i++)
                        lds128(af[i], aBase + ((kcl * 8 + wm * 4 + i) * 128 + lane * 4) * 4);
                    #pragma unroll
                    for (int j = 0; j < 8; j++)
                        lds64(bf[j], bBase + ((kcl * 32 + wn * 8 + j) * 64 + lane * 2) * 4);
                    #pragma unroll
                    for (int i = 0; i < 4; i++)
                        #pragma unroll
                        for (int j = 0; j < 8; j++)
                            mma_tf32(acc[i][j], af[i], bf[j]);
                }
                MBAR_ARRIVE(emptyb + s * 8);     // release before epilogue: producer
            }                                    // may run ahead into next tile

            // ---- epilogue: bias add + fp32 store (overlaps next tile's fill) ----
            const int ncol0 = nt * BN + wn * 64;
            const float* bptr = bias + (size_t)e * NOUT + ncol0;
            #pragma unroll
            for (int j = 0; j < 8; j++) {
                const int cb = j * 8 + (lane & 3) * 2;
                const float bx = __ldg(bptr + cb);
                const float by = __ldg(bptr + cb + 1);
                #pragma unroll
                for (int i = 0; i < 4; i++) {
                    const int r0 = wm * 64 + i * 16 + (lane >> 2);
                    if (mt * BM + r0 < mycnt) {
                        float2 v = make_float2(acc[i][j][0] + bx, acc[i][j][1] + by);
                        *(float2*)(out + (size_t)(m0 + r0) * NOUT + ncol0 + cb) = v;
                    }
                    if (mt * BM + r0 + 8 < mycnt) {
                        float2 v = make_float2(acc[i][j][2] + bx, acc[i][j][3] + by);
                        *(float2*)(out + (size_t)(m0 + r0 + 8) * NOUT + ncol0 + cb) = v;
                    }
                }
            }
        }
    }
}

// ---------------- host launch ----------------
extern "C" void kernel_launch(void* const* d_in, const int* in_sizes, int n_in,
                              void* d_out, int out_size) {
    const float* x    = (const float*)d_in[0];
    const float* w    = (const float*)d_in[1];
    const float* bias = (const float*)d_in[2];
    const int*   tpe  = (const int*)d_in[3];
    float*       out  = (float*)d_out;

    prep_kernel<<<16384, 256>>>(x, w);           // coalesced A+W transform

    cudaFuncSetAttribute(gemm_kernel,
                         cudaFuncAttributeMaxDynamicSharedMemorySize, SMEM_TOTAL);
    int nsm = 148;
    cudaDeviceGetAttribute(&nsm, cudaDevAttrMultiProcessorCount, 0);
    gemm_kernel<<<nsm, NTHREADS, SMEM_TOTAL>>>(bias, tpe, out);  // persistent CTAs
}

// round 13
// speedup vs baseline: 1.0493x; 1.0493x over previous
#include <cuda_runtime.h>
#include <cstdint>

// ---------------- problem constants ----------------
#define NE   8
#define NT   16384
#define NIN  2048
#define NOUT 2048

// ---------------- GEMM tiling (R9-identical) ----------------
#define BM 128
#define BN 256
#define BK 32
#define KITERS (NIN / BK)            // 64
#define STAGES 4
#define A_STAGE_BYTES (BM * BK * 4)  // 16384
#define B_STAGE_BYTES (BN * BK * 4)  // 32768
#define STAGE_BYTES (A_STAGE_BYTES + B_STAGE_BYTES)   // 49152
#define SMEM_CTRL 1024
#define SMEM_TOTAL (SMEM_CTRL + STAGES * STAGE_BYTES) // 197632
#define NTHREADS 320                 // 8 compute warps + 2 producer warps

// ---------------- scratch ----------------
__device__ float g_A[(size_t)NT * NIN];
__device__ float g_W[(size_t)NE * NOUT * NIN];
__device__ int   g_ticket;           // reset to 0 each launch (memsetAsync)

// ---------------- helpers (all plain-sm_103-legal) ----------------
__device__ __forceinline__ uint32_t smem_u32(const void* p) {
    uint32_t a;
    asm("{ .reg .u64 t; cvta.to.shared.u64 t, %1; cvt.u32.u64 %0, t; }" : "=r"(a) : "l"(p));
    return a;
}

__device__ __forceinline__ float tf32r(float f) {
    uint32_t r;
    asm("cvt.rna.tf32.f32 %0, %1;" : "=r"(r) : "f"(f));
    return __uint_as_float(r);
}

__device__ __forceinline__ void cp16(uint32_t smem_dst, const float* gsrc) {
    asm volatile("cp.async.cg.shared.global [%0], [%1], 16;" :: "r"(smem_dst), "l"(gsrc));
}

#define MBAR_INIT(a, c) \
    asm volatile("mbarrier.init.shared.b64 [%0], %1;" :: "r"(a), "r"(c) : "memory")
#define MBAR_ARRIVE(a) \
    asm volatile("mbarrier.arrive.shared.b64 _, [%0];" :: "r"(a) : "memory")
#define CP_MBAR_ARRIVE(a) \
    asm volatile("cp.async.mbarrier.arrive.noinc.shared.b64 [%0];" :: "r"(a) : "memory")

#define MBAR_WAIT(addr, ph) do {                                                   \
    asm volatile("{\n\t.reg .pred P1;\n\t"                                         \
        "WL%=:\n\t"                                                                \
        "mbarrier.try_wait.parity.acquire.cta.shared::cta.b64 P1, [%0], %1, 0x989680;\n\t" \
        "@P1 bra.uni WD%=;\n\t"                                                    \
        "bra.uni WL%=;\n\t"                                                        \
        "WD%=:\n\t}"                                                               \
        :: "r"(addr), "r"(ph) : "memory");                                         \
} while (0)

__device__ __forceinline__ void lds128(uint32_t* r, uint32_t addr) {
    asm volatile("ld.shared.v4.b32 {%0,%1,%2,%3}, [%4];"
                 : "=r"(r[0]), "=r"(r[1]), "=r"(r[2]), "=r"(r[3]) : "r"(addr));
}
__device__ __forceinline__ void lds64(uint32_t* r, uint32_t addr) {
    asm volatile("ld.shared.v2.b32 {%0,%1}, [%2];"
                 : "=r"(r[0]), "=r"(r[1]) : "r"(addr));
}

__device__ __forceinline__ void mma_tf32(float* d, const uint32_t* a, const uint32_t* b) {
    asm volatile(
        "mma.sync.aligned.m16n8k8.row.col.f32.tf32.tf32.f32 "
        "{%0,%1,%2,%3}, {%4,%5,%6,%7}, {%8,%9}, {%0,%1,%2,%3};"
        : "+f"(d[0]), "+f"(d[1]), "+f"(d[2]), "+f"(d[3])
        : "r"(a[0]), "r"(a[1]), "r"(a[2]), "r"(a[3]), "r"(b[0]), "r"(b[1]));
}

// ---------------- coalesced pre-pass (R9-identical, proven) ---------------------
__global__ void __launch_bounds__(256) prep_kernel(const float* __restrict__ x,
                                                   const float* __restrict__ w) {
    __shared__ float s[64 * 68];
    const int tid = threadIdx.x;
    const bool isA = blockIdx.x < 8192;
    const int bi = isA ? blockIdx.x : blockIdx.x - 8192;
    const int rowbase = (bi >> 5) * 64;
    const int colbase = (bi & 31) * 64;
    const float* src = (isA ? x : w) + (size_t)rowbase * NIN + colbase;

    #pragma unroll
    for (int it = 0; it < 4; it++) {
        int L = tid + it * 256;
        int row = L >> 4, ch = L & 15;
        float4 v = *(const float4*)(src + (size_t)row * NIN + ch * 4);
        *(float4*)(&s[row * 68 + ch * 4]) = v;
    }
    __syncthreads();

    const int lane = tid & 31;
    const int wrp  = tid >> 5;
    if (isA) {
        const int b   = rowbase >> 7;
        const int mtb = (rowbase >> 4) & 7;
        const int kc  = (colbase >> 3) + wrp;
        const int lrg = lane >> 2, q = lane & 3;
        const int c   = wrp * 8 + q;
        #pragma unroll
        for (int r = 0; r < 4; r++) {
            const int r0 = r * 16 + lrg;
            float4 o;
            o.x = tf32r(s[r0 * 68 + c]);
            o.y = tf32r(s[(r0 + 8) * 68 + c]);
            o.z = tf32r(s[r0 * 68 + c + 4]);
            o.w = tf32r(s[(r0 + 8) * 68 + c + 4]);
            *(float4*)(g_A + (((size_t)b * 256 + kc) * 8 + (mtb + r)) * 128
                       + lane * 4) = o;
        }
    } else {
        const int nb  = rowbase >> 8;
        const int ntb = (rowbase >> 3) & 31;
        const int kc  = (colbase >> 3) + wrp;
        const int l2  = lane & 15;
        const int hw  = lane >> 4;
        const int ln  = l2 >> 1;
        const int d0  = (l2 & 1) * 4;
        #pragma unroll
        for (int r = 0; r < 4; r++) {
            const int ntL = r * 2 + hw;
            const int row = ntL * 8 + ln;
            const float* sr = &s[row * 68 + wrp * 8];
            float4 o;
            o.x = tf32r(sr[((d0 + 0) >> 1) + 4 * ((d0 + 0) & 1)]);
            o.y = tf32r(sr[((d0 + 1) >> 1) + 4 * ((d0 + 1) & 1)]);
            o.z = tf32r(sr[((d0 + 2) >> 1) + 4 * ((d0 + 2) & 1)]);
            o.w = tf32r(sr[((d0 + 3) >> 1) + 4 * ((d0 + 3) & 1)]);
            *(float4*)(g_W + (((size_t)nb * 256 + kc) * 32 + (ntb + ntL)) * 64
                       + l2 * 4) = o;
        }
    }
}

// write tile descriptor (scheduler thread only); tile order == R9 launch order:
// ticket t -> ti = t >> 3 (A/m tile), nt = t & 7  (consecutive tickets share ti)
__device__ __forceinline__ void write_desc(int* d, int t, const int* __restrict__ tpe,
                                           int ttiles) {
    int e = -1, mt = 0, start = 0, mycnt = 0;
    if (t < ttiles) {
        const int ti = t >> 3;
        int acc = 0, sacc = 0;
        #pragma unroll
        for (int i = 0; i < NE; i++) {
            int cc = __ldg(tpe + i);
            int tiles = (cc + BM - 1) >> 7;
            if (e < 0 && ti < acc + tiles) { e = i; mt = ti - acc; start = sacc; mycnt = cc; }
            acc += tiles; sacc += cc;
        }
    }
    d[0] = e; d[1] = mt; d[2] = start; d[3] = mycnt; d[4] = t & 7;
}

// ---------------- persistent grouped GEMM: ordered-ticket scheduling ------------
__global__ void __launch_bounds__(NTHREADS, 1) gemm_kernel(
        const float* __restrict__ bias,
        const int*   __restrict__ tpe,
        float*       __restrict__ out) {
    extern __shared__ __align__(16) char smem[];

    int ttiles;
    {
        int acc = 0;
        #pragma unroll
        for (int i = 0; i < NE; i++) acc += (__ldg(tpe + i) + BM - 1) >> 7;
        ttiles = acc * 8;
    }

    const int tid = threadIdx.x;
    const uint32_t sb     = smem_u32(smem);
    const uint32_t fullb  = sb;                  // stage fulls: STAGES x 8B
    const uint32_t emptyb = sb + 64;             // stage empties
    const uint32_t tfull  = sb + 128;            // tile-desc fulls: 2 x 8B
    const uint32_t tempty = sb + 160;            // tile-desc empties
    int* desc             = (int*)(smem + 192);  // 2 slots x 8 ints
    const uint32_t dbase  = sb + SMEM_CTRL;

    if (tid == 0) {
        #pragma unroll
        for (int s = 0; s < STAGES; s++) {
            MBAR_INIT(fullb + s * 8, 64);
            MBAR_INIT(emptyb + s * 8, 256);
        }
        #pragma unroll
        for (int s = 0; s < 2; s++) {
            MBAR_INIT(tfull + s * 8, 1);         // armed by scheduler
            MBAR_INIT(tempty + s * 8, NTHREADS); // armed by ALL threads at tile start
        }
    }
    __syncthreads();

    if (tid >= 256) {
        // ================= producer warps (2 warps, 64 threads) =================
        const int ptid = tid - 256;
        if (tid == 256) {                        // scheduler prologue: arm 2 slots
            #pragma unroll
            for (int pre = 0; pre < 2; pre++) {
                int t = atomicAdd(&g_ticket, 1);
                write_desc(desc + pre * 8, t, tpe, ttiles);
                MBAR_ARRIVE(tfull + pre * 8);
            }
        }
        unsigned gk = 0;                         // continuous stage-ring counter
        #pragma unroll 1
        for (unsigned n = 0;; n++) {
            const int slot = n & 1, tph = (n >> 1) & 1;
            MBAR_WAIT(tfull + slot * 8, tph);
            const int e     = desc[slot * 8 + 0];
            const int mt    = desc[slot * 8 + 1];
            const int start = desc[slot * 8 + 2];
            const int nt    = desc[slot * 8 + 4];
            MBAR_ARRIVE(tempty + slot * 8);      // desc consumed (regs)
            if (tid == 256) {                    // refill slot with tile n+2
                MBAR_WAIT(tempty + slot * 8, tph);
                int t = atomicAdd(&g_ticket, 1);
                write_desc(desc + slot * 8, t, tpe, ttiles);
                MBAR_ARRIVE(tfull + slot * 8);
            }
            if (e < 0) break;

            const float* Ab = g_A + (size_t)((start >> 7) + mt) * 256 * 1024;
            const float* Bb = g_W + (size_t)(e * 8 + nt) * 256 * 2048;
            #pragma unroll 1
            for (int k = 0; k < KITERS; k++, gk++) {
                const int s = gk & (STAGES - 1);
                if (gk >= STAGES) MBAR_WAIT(emptyb + s * 8, ((gk >> 2) - 1) & 1);
                const float* As = Ab + (size_t)k * 4096;
                const float* Bs = Bb + (size_t)k * 8192;
                const uint32_t dA = dbase + s * STAGE_BYTES;
                const uint32_t dB = dA + A_STAGE_BYTES;
                #pragma unroll
                for (int i = 0; i < 16; i++)
                    cp16(dA + (ptid + i * 64) * 16, As + (ptid + i * 64) * 4);
                #pragma unroll
                for (int i = 0; i < 32; i++)
                    cp16(dB + (ptid + i * 64) * 16, Bs + (ptid + i * 64) * 4);
                CP_MBAR_ARRIVE(fullb + s * 8);
            }
        }
    } else {
        // ================= compute warps (8 warps, 256 threads) =================
        const int lane = tid & 31;
        const int wid  = tid >> 5;
        const int wm   = wid & 1;
        const int wn   = wid >> 1;

        unsigned gk = 0;
        #pragma unroll 1
        for (unsigned n = 0;; n++) {
            const int slot = n & 1, tph = (n >> 1) & 1;
            MBAR_WAIT(tfull + slot * 8, tph);
            const int e     = desc[slot * 8 + 0];
            const int mt    = desc[slot * 8 + 1];
            const int start = desc[slot * 8 + 2];
            const int mycnt = desc[slot * 8 + 3];
            const int nt    = desc[slot * 8 + 4];
            MBAR_ARRIVE(tempty + slot * 8);      // desc copied to regs
            if (e < 0) break;
            const int m0 = start + mt * BM;

            float acc[4][8][4];
            #pragma unroll
            for (int i = 0; i < 4; i++)
                #pragma unroll
                for (int j = 0; j < 8; j++)
                    #pragma unroll
                    for (int q = 0; q < 4; q++) acc[i][j][q] = 0.0f;

            #pragma unroll 1
            for (int k = 0; k < KITERS; k++, gk++) {
                const int s = gk & (STAGES - 1);
                MBAR_WAIT(fullb + s * 8, (gk >> 2) & 1);
                const uint32_t aBase = dbase + s * STAGE_BYTES;
                const uint32_t bBase = aBase + A_STAGE_BYTES;
                #pragma unroll
                for (int kcl = 0; kcl < 4; kcl++) {
                    uint32_t af[4][4], bf[8][2];
                    #pragma unroll
                    for (int i = 0; i < 4; i++)
                        lds128(af[i], aBase + ((kcl * 8 + wm * 4 + i) * 128 + lane * 4) * 4);
                    #pragma unroll
                    for (int j = 0; j < 8; j++)
                        lds64(bf[j], bBase + ((kcl * 32 + wn * 8 + j) * 64 + lane * 2) * 4);
                    #pragma unroll
                    for (int i = 0; i < 4; i++)
                        #pragma unroll
                        for (int j = 0; j < 8; j++)
                            mma_tf32(acc[i][j], af[i], bf[j]);
                }
                MBAR_ARRIVE(emptyb + s * 8);     // producer may run into next tile
            }

            // ---- epilogue (desc in regs; overlaps next tile's fill) ----
            const int ncol0 = nt * BN + wn * 64;
            const float* bptr = bias + (size_t)e * NOUT + ncol0;
            #pragma unroll
            for (int j = 0; j < 8; j++) {
                const int cb = j * 8 + (lane & 3) * 2;
                const float bx = __ldg(bptr + cb);
                const float by = __ldg(bptr + cb + 1);
                #pragma unroll
                for (int i = 0; i < 4; i++) {
                    const int r0 = wm * 64 + i * 16 + (lane >> 2);
                    if (mt * BM + r0 < mycnt) {
                        float2 v = make_float2(acc[i][j][0] + bx, acc[i][j][1] + by);
                        *(float2*)(out + (size_t)(m0 + r0) * NOUT + ncol0 + cb) = v;
                    }
                    if (mt * BM + r0 + 8 < mycnt) {
                        float2 v = make_float2(acc[i][j][2] + bx, acc[i][j][3] + by);
                        *(float2*)(out + (size_t)(m0 + r0 + 8) * NOUT + ncol0 + cb) = v;
                    }
                }
            }
        }
    }
}

// ---------------- host launch ----------------
extern "C" void kernel_launch(void* const* d_in, const int* in_sizes, int n_in,
                              void* d_out, int out_size) {
    const float* x    = (const float*)d_in[0];
    const float* w    = (const float*)d_in[1];
    const float* bias = (const float*)d_in[2];
    const int*   tpe  = (const int*)d_in[3];
    float*       out  = (float*)d_out;

    void* pt = nullptr;
    cudaGetSymbolAddress(&pt, g_ticket);
    cudaMemsetAsync(pt, 0, sizeof(int));         // reset ticket each launch

    prep_kernel<<<16384, 256>>>(x, w);

    cudaFuncSetAttribute(gemm_kernel,
                         cudaFuncAttributeMaxDynamicSharedMemorySize, SMEM_TOTAL);
    int nsm = 148;
    cudaDeviceGetAttribute(&nsm, cudaDevAttrMultiProcessorCount, 0);
    gemm_kernel<<<nsm, NTHREADS, SMEM_TOTAL>>>(bias, tpe, out);
}

// round 14
// speedup vs baseline: 1.1742x; 1.1190x over previous
#include <cuda_runtime.h>
#include <cstdint>

// ---------------- problem constants ----------------
#define NE   8
#define NT   16384
#define NIN  2048
#define NOUT 2048

// ---------------- GEMM tiling (R9-identical) ----------------
#define BM 128
#define BN 256
#define BK 32
#define KITERS (NIN / BK)            // 64
#define STAGES 4
#define A_STAGE_BYTES (BM * BK * 4)  // 16384
#define B_STAGE_BYTES (BN * BK * 4)  // 32768
#define STAGE_BYTES (A_STAGE_BYTES + B_STAGE_BYTES)   // 49152
#define SMEM_CTRL 1024
#define SMEM_TOTAL (SMEM_CTRL + STAGES * STAGE_BYTES) // 197632
#define NTHREADS 320                 // 8 compute warps + 2 producer warps
#define MAXTILES 136

// ---------------- scratch: tf32-rounded, fragment-native layouts ----------------
__device__ float g_A[(size_t)NT * NIN];
__device__ float g_W[(size_t)NE * NOUT * NIN];

// ---------------- helpers (all plain-sm_103-legal) ----------------
__device__ __forceinline__ uint32_t smem_u32(const void* p) {
    uint32_t a;
    asm("{ .reg .u64 t; cvta.to.shared.u64 t, %1; cvt.u32.u64 %0, t; }" : "=r"(a) : "l"(p));
    return a;
}

__device__ __forceinline__ float tf32r(float f) {
    uint32_t r;
    asm("cvt.rna.tf32.f32 %0, %1;" : "=r"(r) : "f"(f));
    return __uint_as_float(r);
}

__device__ __forceinline__ void cp16(uint32_t smem_dst, const float* gsrc) {
    asm volatile("cp.async.cg.shared.global [%0], [%1], 16;" :: "r"(smem_dst), "l"(gsrc));
}

#define MBAR_INIT(a, c) \
    asm volatile("mbarrier.init.shared.b64 [%0], %1;" :: "r"(a), "r"(c) : "memory")
#define MBAR_ARRIVE(a) \
    asm volatile("mbarrier.arrive.shared.b64 _, [%0];" :: "r"(a) : "memory")
#define CP_MBAR_ARRIVE(a) \
    asm volatile("cp.async.mbarrier.arrive.noinc.shared.b64 [%0];" :: "r"(a) : "memory")

#define MBAR_WAIT(addr, ph) do {                                                   \
    asm volatile("{\n\t.reg .pred P1;\n\t"                                         \
        "WL%=:\n\t"                                                                \
        "mbarrier.try_wait.parity.acquire.cta.shared::cta.b64 P1, [%0], %1, 0x989680;\n\t" \
        "@P1 bra.uni WD%=;\n\t"                                                    \
        "bra.uni WL%=;\n\t"                                                        \
        "WD%=:\n\t}"                                                               \
        :: "r"(addr), "r"(ph) : "memory");                                         \
} while (0)

__device__ __forceinline__ void lds128(uint32_t* r, uint32_t addr) {
    asm volatile("ld.shared.v4.b32 {%0,%1,%2,%3}, [%4];"
                 : "=r"(r[0]), "=r"(r[1]), "=r"(r[2]), "=r"(r[3]) : "r"(addr));
}
__device__ __forceinline__ void lds64(uint32_t* r, uint32_t addr) {
    asm volatile("ld.shared.v2.b32 {%0,%1}, [%2];"
                 : "=r"(r[0]), "=r"(r[1]) : "r"(addr));
}

__device__ __forceinline__ void mma_tf32(float* d, const uint32_t* a, const uint32_t* b) {
    asm volatile(
        "mma.sync.aligned.m16n8k8.row.col.f32.tf32.tf32.f32 "
        "{%0,%1,%2,%3}, {%4,%5,%6,%7}, {%8,%9}, {%0,%1,%2,%3};"
        : "+f"(d[0]), "+f"(d[1]), "+f"(d[2]), "+f"(d[3])
        : "r"(a[0]), "r"(a[1]), "r"(a[2]), "r"(a[3]), "r"(b[0]), "r"(b[1]));
}

// ---------------- coalesced pre-pass (R9-identical, proven) ---------------------
__global__ void __launch_bounds__(256) prep_kernel(const float* __restrict__ x,
                                                   const float* __restrict__ w) {
    __shared__ float s[64 * 68];
    const int tid = threadIdx.x;
    const bool isA = blockIdx.x < 8192;
    const int bi = isA ? blockIdx.x : blockIdx.x - 8192;
    const int rowbase = (bi >> 5) * 64;
    const int colbase = (bi & 31) * 64;
    const float* src = (isA ? x : w) + (size_t)rowbase * NIN + colbase;

    #pragma unroll
    for (int it = 0; it < 4; it++) {
        int L = tid + it * 256;
        int row = L >> 4, ch = L & 15;
        float4 v = *(const float4*)(src + (size_t)row * NIN + ch * 4);
        *(float4*)(&s[row * 68 + ch * 4]) = v;
    }
    __syncthreads();

    const int lane = tid & 31;
    const int wrp  = tid >> 5;
    if (isA) {
        const int b   = rowbase >> 7;
        const int mtb = (rowbase >> 4) & 7;
        const int kc  = (colbase >> 3) + wrp;
        const int lrg = lane >> 2, q = lane & 3;
        const int c   = wrp * 8 + q;
        #pragma unroll
        for (int r = 0; r < 4; r++) {
            const int r0 = r * 16 + lrg;
            float4 o;
            o.x = tf32r(s[r0 * 68 + c]);
            o.y = tf32r(s[(r0 + 8) * 68 + c]);
            o.z = tf32r(s[r0 * 68 + c + 4]);
            o.w = tf32r(s[(r0 + 8) * 68 + c + 4]);
            *(float4*)(g_A + (((size_t)b * 256 + kc) * 8 + (mtb + r)) * 128
                       + lane * 4) = o;
        }
    } else {
        const int nb  = rowbase >> 8;
        const int ntb = (rowbase >> 3) & 31;
        const int kc  = (colbase >> 3) + wrp;
        const int l2  = lane & 15;
        const int hw  = lane >> 4;
        const int ln  = l2 >> 1;
        const int d0  = (l2 & 1) * 4;
        #pragma unroll
        for (int r = 0; r < 4; r++) {
            const int ntL = r * 2 + hw;
            const int row = ntL * 8 + ln;
            const float* sr = &s[row * 68 + wrp * 8];
            float4 o;
            o.x = tf32r(sr[((d0 + 0) >> 1) + 4 * ((d0 + 0) & 1)]);
            o.y = tf32r(sr[((d0 + 1) >> 1) + 4 * ((d0 + 1) & 1)]);
            o.z = tf32r(sr[((d0 + 2) >> 1) + 4 * ((d0 + 2) & 1)]);
            o.w = tf32r(sr[((d0 + 3) >> 1) + 4 * ((d0 + 3) & 1)]);
            *(float4*)(g_W + (((size_t)nb * 256 + kc) * 32 + (ntb + ntL)) * 64
                       + l2 * 4) = o;
        }
    }
}

// ---------------- main grouped GEMM: R9 pipeline + paired consumer waits --------
__global__ void __launch_bounds__(NTHREADS, 1) gemm_kernel(
        const float* __restrict__ bias,
        const int*   __restrict__ tpe,
        float*       __restrict__ out) {
    extern __shared__ __align__(16) char smem[];

    const int nt = blockIdx.x;
    const int ti = blockIdx.y;

    int e = -1, mt = 0, start = 0, mycnt = 0;
    {
        int acc = 0, sacc = 0;
        #pragma unroll
        for (int i = 0; i < NE; i++) {
            int cc = __ldg(tpe + i);
            int tiles = (cc + BM - 1) >> 7;
            if (e < 0 && ti < acc + tiles) { e = i; mt = ti - acc; start = sacc; mycnt = cc; }
            acc += tiles; sacc += cc;
        }
    }
    if (e < 0) return;

    const int tid  = threadIdx.x;
    const int b    = (start >> 7) + mt;
    const int nb   = e * 8 + nt;
    const int m0   = start + mt * BM;

    const uint32_t sb     = smem_u32(smem);
    const uint32_t fullb  = sb;
    const uint32_t emptyb = sb + 64;
    const uint32_t dbase  = sb + SMEM_CTRL;

    const float* Ab = g_A + (size_t)b  * 256 * 1024;
    const float* Bb = g_W + (size_t)nb * 256 * 2048;

    if (tid == 0) {
        #pragma unroll
        for (int s = 0; s < STAGES; s++) {
            MBAR_INIT(fullb + s * 8, 64);
            MBAR_INIT(emptyb + s * 8, 256);
        }
    }
    __syncthreads();

    if (tid >= 256) {
        // ================= producer warps (R9-identical) ========================
        const int ptid = tid - 256;
        #pragma unroll 1
        for (int k = 0; k < KITERS; k++) {
            const int s = k & (STAGES - 1);
            if (k >= STAGES) MBAR_WAIT(emptyb + s * 8, ((k >> 2) - 1) & 1);
            const float* As = Ab + (size_t)k * 4096;
            const float* Bs = Bb + (size_t)k * 8192;
            const uint32_t dA = dbase + s * STAGE_BYTES;
            const uint32_t dB = dA + A_STAGE_BYTES;
            #pragma unroll
            for (int i = 0; i < 16; i++)
                cp16(dA + (ptid + i * 64) * 16, As + (ptid + i * 64) * 4);
            #pragma unroll
            for (int i = 0; i < 32; i++)
                cp16(dB + (ptid + i * 64) * 16, Bs + (ptid + i * 64) * 4);
            CP_MBAR_ARRIVE(fullb + s * 8);
        }
    } else {
        // ====== compute warps: paired waits (full[s+1] implies full[s]) =========
        // cp.async commit-groups complete in per-thread program order, and the
        // noinc arrive fires after ALL of that thread's prior cp.asyncs. So all
        // 64 arrivals at full[s+1] imply all 64 at full[s]; one acquire covers
        // the pair. 32 waits/tile instead of 64.
        const int lane = tid & 31;
        const int wid  = tid >> 5;
        const int wm   = wid & 1;
        const int wn   = wid >> 1;

        float acc[4][8][4];
        #pragma unroll
        for (int i = 0; i < 4; i++)
            #pragma unroll
            for (int j = 0; j < 8; j++)
                #pragma unroll
                for (int q = 0; q < 4; q++) acc[i][j][q] = 0.0f;

        #pragma unroll 1
        for (int p = 0; p < KITERS / 2; p++) {
            const int s0 = (p & 1) << 1;                 // stage pair {0,1} or {2,3}
            MBAR_WAIT(fullb + (s0 + 1) * 8, (p >> 1) & 1);
            #pragma unroll
            for (int h = 0; h < 2; h++) {
                const int s = s0 + h;
                const uint32_t aBase = dbase + s * STAGE_BYTES;
                const uint32_t bBase = aBase + A_STAGE_BYTES;
                #pragma unroll
                for (int kcl = 0; kcl < 4; kcl++) {
                    uint32_t af[4][4], bf[8][2];
                    #pragma unroll
                    for (int i = 0; i < 4; i++)
                        lds128(af[i], aBase + ((kcl * 8 + wm * 4 + i) * 128 + lane * 4) * 4);
                    #pragma unroll
                    for (int j = 0; j < 8; j++)
                        lds64(bf[j], bBase + ((kcl * 32 + wn * 8 + j) * 64 + lane * 2) * 4);
                    #pragma unroll
                    for (int i = 0; i < 4; i++)
                        #pragma unroll
                        for (int j = 0; j < 8; j++)
                            mma_tf32(acc[i][j], af[i], bf[j]);
                }
                MBAR_ARRIVE(emptyb + s * 8);     // per-stage release (producer pacing
            }                                    // unchanged vs R9)
        }

        // ---- epilogue: bias add + fp32 store (R9-identical) ----
        const int ncol0 = nt * BN + wn * 64;
        const float* bptr = bias + (size_t)e * NOUT + ncol0;
        #pragma unroll
        for (int j = 0; j < 8; j++) {
            const int cb = j * 8 + (lane & 3) * 2;
            const float bx = __ldg(bptr + cb);
            const float by = __ldg(bptr + cb + 1);
            #pragma unroll
            for (int i = 0; i < 4; i++) {
                const int r0 = wm * 64 + i * 16 + (lane >> 2);
                if (mt * BM + r0 < mycnt) {
                    float2 v = make_float2(acc[i][j][0] + bx, acc[i][j][1] + by);
                    *(float2*)(out + (size_t)(m0 + r0) * NOUT + ncol0 + cb) = v;
                }
                if (mt * BM + r0 + 8 < mycnt) {
                    float2 v = make_float2(acc[i][j][2] + bx, acc[i][j][3] + by);
                    *(float2*)(out + (size_t)(m0 + r0 + 8) * NOUT + ncol0 + cb) = v;
                }
            }
        }
    }
}

// ---------------- host launch ----------------
extern "C" void kernel_launch(void* const* d_in, const int* in_sizes, int n_in,
                              void* d_out, int out_size) {
    const float* x    = (const float*)d_in[0];
    const float* w    = (const float*)d_in[1];
    const float* bias = (const float*)d_in[2];
    const int*   tpe  = (const int*)d_in[3];
    float*       out  = (float*)d_out;

    prep_kernel<<<16384, 256>>>(x, w);

    cudaFuncSetAttribute(gemm_kernel,
                         cudaFuncAttributeMaxDynamicSharedMemorySize, SMEM_TOTAL);
    dim3 grid(NOUT / BN, MAXTILES);              // R9 launch order (L2-friendly)
    gemm_kernel<<<grid, NTHREADS, SMEM_TOTAL>>>(bias, tpe, out);
}